// round 8
// baseline (speedup 1.0000x reference)
#include <cuda_runtime.h>
#include <stdint.h>
#include <float.h>

// Shapes: data [64,1024,256] f32, locs [64,256,2] f32, out [64,1024,2500] f32
#define B_  64
#define T_  1024
#define N_  256
#define G_  50
#define GG  2500
#define TPB 256
#define T_PER_BLOCK 32            // t-rows gathered per block
#define R_  8                     // t-rows per barrier window
#define SLOTS 32                  // blocks per batch
#define CELLS_PER_SLOT 80         // 31*80 + 20 = 2500
#define SPIN_LIMIT 2000000        // pathological-schedule fallback threshold

__device__ uint8_t  g_nearest[B_ * GG];
__device__ unsigned g_ready[B_];   // producer slices published (0..32)
__device__ unsigned g_done[B_];    // gather blocks finished (0..32)

union SmemU {
    struct { float sx[N_], sy[N_], sc[N_]; } p;                    // producer: 3 KB
    struct { float4 rowsA[N_], rowsB[N_]; uint8_t sidx[GG]; } g;   // gather: 10.7 KB
};

// ---------------------------------------------------------------------------
// Producer slice: cells [cbase, cbase+ncells) of batch b, warp-per-cell.
// Lane evaluates 8 sensors' prefilter key e_j = c_j - 2sx*gx - 2sy*gy
//   (|e - shifted d2| <= ~3e-3; fp32 sqrt-tie class width <= ~1.5e-3, so
//    thresh = emin + 0.02 covers all possible winners). For rare e<=thresh,
// EXACT reference d2 (rn mul/add, no contraction) + __fsqrt_rn, packed as
// (bits(sq)<<32)|j and 64-bit min-reduced => lexicographic (sq, j) min
// = first-index-wins, bit-identical to jnp.argmin(sqrt(...)).
// Deterministic => byte-idempotent (safe to produce redundantly).
// ---------------------------------------------------------------------------
__device__ __forceinline__ void produce_slice(const SmemU& sm, int b,
                                              int cbase, int ncells,
                                              int wid, int lane) {
    for (int c = wid; c < ncells; c += 8) {               // warp-per-cell
        const int cell = cbase + c;
        const float gx = (float)(cell / G_);
        const float gy = (float)(cell % G_);
        const float ax = -2.0f * gx, ay = -2.0f * gy;     // exact small ints

        float e[8];
        float emin = FLT_MAX;
        #pragma unroll
        for (int i = 0; i < 8; ++i) {
            int j = lane + 32 * i;                        // conflict-free LDS
            e[i] = __fmaf_rn(sm.p.sy[j], ay, __fmaf_rn(sm.p.sx[j], ax, sm.p.sc[j]));
            emin = fminf(emin, e[i]);
        }
        #pragma unroll
        for (int o = 16; o > 0; o >>= 1)
            emin = fminf(emin, __shfl_xor_sync(0xFFFFFFFFu, emin, o));
        const float thresh = emin + 0.02f;

        unsigned long long key = ~0ull;
        #pragma unroll
        for (int i = 0; i < 8; ++i) {
            if (e[i] <= thresh) {                         // ~1 lane-hit per cell
                int j = lane + 32 * i;
                float dx = __fsub_rn(sm.p.sx[j], gx);
                float dy = __fsub_rn(sm.p.sy[j], gy);
                float d2 = __fadd_rn(__fmul_rn(dx, dx), __fmul_rn(dy, dy));
                float sq = __fsqrt_rn(d2);                // exact reference value
                unsigned long long k =
                    ((unsigned long long)__float_as_uint(sq) << 32) | (unsigned)j;
                key = (k < key) ? k : key;
            }
        }
        #pragma unroll
        for (int o = 16; o > 0; o >>= 1) {
            unsigned long long other = __shfl_xor_sync(0xFFFFFFFFu, key, o);
            key = (other < key) ? other : key;
        }
        if (lane == 0)
            g_nearest[b * GG + cell] = (uint8_t)(key & 0xFFu);
    }
}

// ---------------------------------------------------------------------------
// Fused kernel. Block (b = bid>>5, slot = bid&31):
//  1) produce this slot's 1/32 of batch b's nearest map (hides in the other
//     blocks' memory-bound gather issue slack),
//  2) publish, spin until batch complete — with bounded spin + idempotent
//     full-batch fallback => terminates under ANY block schedule,
//  3) gather out[b, t0..t0+31, :] = data[b, t, nearest[b,:]] (R6 body).
//  Replay-safe: last done-block of each batch resets its flags to zero.
// ---------------------------------------------------------------------------
__global__ __launch_bounds__(TPB)
void fused_kernel(const float* __restrict__ data,
                  const float* __restrict__ locs,
                  float* __restrict__ out) {
    __shared__ SmemU sm;
    __shared__ int s_fallback;

    const int bid  = blockIdx.x;
    const int tid  = threadIdx.x;
    const int b    = bid >> 5;
    const int slot = bid & 31;
    const int lane = tid & 31;
    const int wid  = tid >> 5;

    // ---- load + transform sensor table -----------------------------------
    {
        float2 l = reinterpret_cast<const float2*>(locs)[b * N_ + tid];
        float sx = __fadd_rn(__fmul_rn(l.x, 25.0f), 25.0f);   // exact ref transform
        float sy = __fadd_rn(__fmul_rn(l.y, 25.0f), 25.0f);
        sm.p.sx[tid] = sx;
        sm.p.sy[tid] = sy;
        sm.p.sc[tid] = sx * sx + sy * sy;
    }
    if (tid == 0) s_fallback = 0;
    __syncthreads();

    // ---- producer slice ---------------------------------------------------
    const int cbase = slot * CELLS_PER_SLOT;
    produce_slice(sm, b, cbase, min(CELLS_PER_SLOT, GG - cbase), wid, lane);

    // ---- publish + bounded wait -------------------------------------------
    __threadfence();                       // release g_nearest slice
    __syncthreads();
    if (tid == 0) {
        atomicAdd(&g_ready[b], 1u);
        long long spins = 0;
        while (atomicAdd(&g_ready[b], 0u) < SLOTS) {
            __nanosleep(64);
            if (++spins > SPIN_LIMIT) { s_fallback = 1; break; }
        }
    }
    __syncthreads();
    if (s_fallback) {
        // pathological schedule: produce the whole batch ourselves
        // (deterministic + idempotent => concurrent duplicates are benign)
        for (int s2 = 0; s2 < SLOTS; ++s2) {
            int cb = s2 * CELLS_PER_SLOT;
            produce_slice(sm, b, cb, min(CELLS_PER_SLOT, GG - cb), wid, lane);
        }
        __syncthreads();
    }
    __threadfence();                       // acquire other slices

    // ---- gather phase (R6 body) --------------------------------------------
    {   // stage indices via L2 (bypass any stale L1)
        const uint32_t* src = reinterpret_cast<const uint32_t*>(g_nearest + (size_t)b * GG);
        uint32_t* dst = reinterpret_cast<uint32_t*>(sm.g.sidx);
        #pragma unroll
        for (int k = tid; k < GG / 4; k += TPB) dst[k] = __ldcg(src + k);
    }
    __syncthreads();

    int idx[3][4];
    #pragma unroll
    for (int gi = 0; gi < 3; ++gi) {
        int k = tid + gi * TPB;
        if (k < GG / 4) {
            idx[gi][0] = sm.g.sidx[4 * k + 0];
            idx[gi][1] = sm.g.sidx[4 * k + 1];
            idx[gi][2] = sm.g.sidx[4 * k + 2];
            idx[gi][3] = sm.g.sidx[4 * k + 3];
        }
    }

    const int t0 = slot * T_PER_BLOCK;
    const float* dbase = data + ((size_t)b * T_ + t0) * (size_t)N_;
    float*       obase = out  + ((size_t)b * T_ + t0) * (size_t)GG;

    #pragma unroll 1
    for (int w = 0; w < T_PER_BLOCK / R_; ++w) {
        __syncthreads();
        {
            const float* d0 = dbase + (size_t)(w * R_) * N_ + tid;
            float4 va, vb;
            va.x = __ldcs(d0 + 0 * N_);
            va.y = __ldcs(d0 + 1 * N_);
            va.z = __ldcs(d0 + 2 * N_);
            va.w = __ldcs(d0 + 3 * N_);
            vb.x = __ldcs(d0 + 4 * N_);
            vb.y = __ldcs(d0 + 5 * N_);
            vb.z = __ldcs(d0 + 6 * N_);
            vb.w = __ldcs(d0 + 7 * N_);
            sm.g.rowsA[tid] = va;
            sm.g.rowsB[tid] = vb;
        }
        __syncthreads();

        float* o = obase + (size_t)(w * R_) * GG;
        #pragma unroll
        for (int gi = 0; gi < 3; ++gi) {
            int k = tid + gi * TPB;
            if (k < GG / 4) {
                float4 a0 = sm.g.rowsA[idx[gi][0]];
                float4 a1 = sm.g.rowsA[idx[gi][1]];
                float4 a2 = sm.g.rowsA[idx[gi][2]];
                float4 a3 = sm.g.rowsA[idx[gi][3]];
                __stcs(reinterpret_cast<float4*>(o + 0 * GG) + k,
                       make_float4(a0.x, a1.x, a2.x, a3.x));
                __stcs(reinterpret_cast<float4*>(o + 1 * GG) + k,
                       make_float4(a0.y, a1.y, a2.y, a3.y));
                __stcs(reinterpret_cast<float4*>(o + 2 * GG) + k,
                       make_float4(a0.z, a1.z, a2.z, a3.z));
                __stcs(reinterpret_cast<float4*>(o + 3 * GG) + k,
                       make_float4(a0.w, a1.w, a2.w, a3.w));
                float4 b0 = sm.g.rowsB[idx[gi][0]];
                float4 b1 = sm.g.rowsB[idx[gi][1]];
                float4 b2 = sm.g.rowsB[idx[gi][2]];
                float4 b3 = sm.g.rowsB[idx[gi][3]];
                __stcs(reinterpret_cast<float4*>(o + 4 * GG) + k,
                       make_float4(b0.x, b1.x, b2.x, b3.x));
                __stcs(reinterpret_cast<float4*>(o + 5 * GG) + k,
                       make_float4(b0.y, b1.y, b2.y, b3.y));
                __stcs(reinterpret_cast<float4*>(o + 6 * GG) + k,
                       make_float4(b0.z, b1.z, b2.z, b3.z));
                __stcs(reinterpret_cast<float4*>(o + 7 * GG) + k,
                       make_float4(b0.w, b1.w, b2.w, b3.w));
            }
        }
    }

    // ---- replay-safe reset --------------------------------------------------
    __syncthreads();
    if (tid == 0) {
        unsigned o = atomicAdd(&g_done[b], 1u);
        if (o == SLOTS - 1u) {            // last block of batch: clear flags
            g_done[b]  = 0u;
            g_ready[b] = 0u;
        }
    }
}

// ---------------------------------------------------------------------------
extern "C" void kernel_launch(void* const* d_in, const int* in_sizes, int n_in,
                              void* d_out, int out_size) {
    const float* data = (const float*)d_in[0];
    const float* locs = (const float*)d_in[1];
    if (n_in >= 2 && in_sizes[0] < in_sizes[1]) {
        data = (const float*)d_in[1];
        locs = (const float*)d_in[0];
    }
    float* out = (float*)d_out;

    fused_kernel<<<B_ * SLOTS, TPB>>>(data, locs, out);
}

// round 9
// speedup vs baseline: 1.0041x; 1.0041x over previous
#include <cuda_runtime.h>
#include <stdint.h>
#include <float.h>

// Shapes: data [64,1024,256] f32, locs [64,256,2] f32, out [64,1024,2500] f32
#define B_   64
#define T_   1024
#define N_   256
#define G_   50
#define GG   2500
#define TPB  256
#define R_   8                       // t-rows per gather item
#define SLICES 320                   // 64 batches x 5 slices of 512 cells
#define CELLS_PER_SLICE 512
#define ITEMS (B_ * (T_ / R_))       // 8192 gather items
#define SPIN_LIMIT 200000            // pathological-schedule fallback bound

__device__ uint8_t  g_nearest[B_ * GG];
__device__ unsigned g_arrive;        // device-barrier arrivals
__device__ unsigned g_ticket;        // gather work-item ticket
__device__ unsigned g_finish;        // completion counter (drives replay reset)

union SmemU {
    struct { float4 sen[N_]; } p;                                   // producer
    struct { float4 rowsA[N_], rowsB[N_]; uint8_t sidx[GG]; } g;    // gather
};

// ---------------------------------------------------------------------------
// Producer slice s: cells [ (s%5)*512, +512 ) of batch s/5, 2 cells/thread.
// Exact jnp.argmin(sqrt(dx^2+dy^2)) reproduction (validated rel_err=0):
//  Pass 1: branchless min of e_j = c_j - 2sx*gx - 2sy*gy (|e err| <= ~3e-3;
//          sqrt-tie class width <= ~1.5e-3 => thresh = emin+0.02 is safe).
//  Pass 2: exact rn-rounded d2 (no FMA contraction) + __fsqrt_rn for rare
//          candidates; strict < ascending j => first-index-wins.
// Deterministic => byte-idempotent (redundant production is harmless).
// ---------------------------------------------------------------------------
__device__ __forceinline__ void produce_slice(SmemU& sm, int s,
                                              const float* __restrict__ locs,
                                              int tid) {
    const int b     = s / 5;
    const int cbase = (s % 5) * CELLS_PER_SLICE;

    __syncthreads();                 // protect sen[] reuse
    {
        float2 l = reinterpret_cast<const float2*>(locs)[b * N_ + tid];
        float sx = __fadd_rn(__fmul_rn(l.x, 25.0f), 25.0f);   // exact ref transform
        float sy = __fadd_rn(__fmul_rn(l.y, 25.0f), 25.0f);
        sm.p.sen[tid] = make_float4(sx, sy, sx * sx + sy * sy, 0.0f);
    }
    __syncthreads();

    const int g0 = cbase + tid;
    const int g1 = g0 + TPB;
    const float gxa = (float)(g0 / G_), gya = (float)(g0 % G_);
    const float gxb = (float)(g1 / G_), gyb = (float)(g1 % G_);
    const float axa = -2.0f * gxa, aya = -2.0f * gya;         // exact small ints
    const float axb = -2.0f * gxb, ayb = -2.0f * gyb;

    float ma0 = FLT_MAX, ma1 = FLT_MAX, mb0 = FLT_MAX, mb1 = FLT_MAX;
    #pragma unroll 8
    for (int j = 0; j < N_; j += 2) {
        float4 s0 = sm.p.sen[j];
        float4 s1 = sm.p.sen[j + 1];
        ma0 = fminf(ma0, __fmaf_rn(s0.y, aya, __fmaf_rn(s0.x, axa, s0.z)));
        mb0 = fminf(mb0, __fmaf_rn(s0.y, ayb, __fmaf_rn(s0.x, axb, s0.z)));
        ma1 = fminf(ma1, __fmaf_rn(s1.y, aya, __fmaf_rn(s1.x, axa, s1.z)));
        mb1 = fminf(mb1, __fmaf_rn(s1.y, ayb, __fmaf_rn(s1.x, axb, s1.z)));
    }
    const float ta = fminf(ma0, ma1) + 0.02f;
    const float tb = fminf(mb0, mb1) + 0.02f;

    float bsa = FLT_MAX, bsb = FLT_MAX;
    int   bia = 0,       bib = 0;
    #pragma unroll 4
    for (int j = 0; j < N_; ++j) {
        float4 sv = sm.p.sen[j];
        float ea = __fmaf_rn(sv.y, aya, __fmaf_rn(sv.x, axa, sv.z));
        float eb = __fmaf_rn(sv.y, ayb, __fmaf_rn(sv.x, axb, sv.z));
        if (ea <= ta) {                                       // ~1 hit per cell
            float dx = __fsub_rn(sv.x, gxa);
            float dy = __fsub_rn(sv.y, gya);
            float d2 = __fadd_rn(__fmul_rn(dx, dx), __fmul_rn(dy, dy));
            float sq = __fsqrt_rn(d2);
            if (sq < bsa) { bsa = sq; bia = j; }
        }
        if (eb <= tb) {
            float dx = __fsub_rn(sv.x, gxb);
            float dy = __fsub_rn(sv.y, gyb);
            float d2 = __fadd_rn(__fmul_rn(dx, dx), __fmul_rn(dy, dy));
            float sq = __fsqrt_rn(d2);
            if (sq < bsb) { bsb = sq; bib = j; }
        }
    }
    if (g0 < GG) g_nearest[b * GG + g0] = (uint8_t)bia;
    if (g1 < GG) g_nearest[b * GG + g1] = (uint8_t)bib;
}

// ---------------------------------------------------------------------------
// Persistent kernel: grid = 3 x numSMs (all blocks co-resident by
// __launch_bounds__(256,3) => the arrive-counter barrier is schedule-safe;
// bounded spin + idempotent fallback makes termination unconditional).
// ---------------------------------------------------------------------------
__global__ __launch_bounds__(TPB, 3)
void persistent_kernel(const float* __restrict__ data,
                       const float* __restrict__ locs,
                       float* __restrict__ out) {
    __shared__ SmemU sm;
    __shared__ int s_item;
    __shared__ int s_curb;
    __shared__ int s_timeout;

    const int tid = threadIdx.x;

    // ---- phase 1: produce nearest-index slices (grid-stride) -------------
    for (int s = blockIdx.x; s < SLICES; s += gridDim.x)
        produce_slice(sm, s, locs, tid);

    // ---- device barrier ----------------------------------------------------
    __threadfence();                           // release g_nearest writes
    __syncthreads();
    if (tid == 0) {
        s_timeout = 0;
        atomicAdd(&g_arrive, 1u);
        int spins = 0;
        while (atomicAdd(&g_arrive, 0u) < gridDim.x) {
            __nanosleep(64);
            if (++spins > SPIN_LIMIT) { s_timeout = 1; break; }
        }
    }
    __syncthreads();
    if (s_timeout) {                           // unreachable under co-residency
        for (int s = 0; s < SLICES; ++s)       // idempotent full production
            produce_slice(sm, s, locs, tid);
        __syncthreads();
    }
    __threadfence();                           // acquire all slices

    // ---- phase 2: gather via ticket scheduler -----------------------------
    if (tid == 0) s_curb = -1;
    int idx[3][4];

    for (;;) {
        __syncthreads();                       // smem reuse + s_item/s_curb
        if (tid == 0) s_item = (int)atomicAdd(&g_ticket, 1u);
        __syncthreads();
        const int item = s_item;
        if (item >= ITEMS) break;

        const int b  = item >> 7;              // 128 windows per batch
        const int t0 = (item & 127) * R_;

        if (b != s_curb) {                     // restage this batch's indices
            const uint32_t* src =
                reinterpret_cast<const uint32_t*>(g_nearest + (size_t)b * GG);
            uint32_t* dst = reinterpret_cast<uint32_t*>(sm.g.sidx);
            #pragma unroll
            for (int k = tid; k < GG / 4; k += TPB) dst[k] = __ldcg(src + k);
            if (tid == 0) s_curb = b;
            __syncthreads();
            #pragma unroll
            for (int gi = 0; gi < 3; ++gi) {
                int k = tid + gi * TPB;
                if (k < GG / 4) {
                    idx[gi][0] = sm.g.sidx[4 * k + 0];
                    idx[gi][1] = sm.g.sidx[4 * k + 1];
                    idx[gi][2] = sm.g.sidx[4 * k + 2];
                    idx[gi][3] = sm.g.sidx[4 * k + 3];
                }
            }
        }

        // stage 8 t-rows transposed (thread tid owns sensor tid)
        {
            const float* d0 = data + ((size_t)b * T_ + t0) * (size_t)N_ + tid;
            float4 va, vb;
            va.x = __ldcs(d0 + 0 * N_);
            va.y = __ldcs(d0 + 1 * N_);
            va.z = __ldcs(d0 + 2 * N_);
            va.w = __ldcs(d0 + 3 * N_);
            vb.x = __ldcs(d0 + 4 * N_);
            vb.y = __ldcs(d0 + 5 * N_);
            vb.z = __ldcs(d0 + 6 * N_);
            vb.w = __ldcs(d0 + 7 * N_);
            sm.g.rowsA[tid] = va;
            sm.g.rowsB[tid] = vb;
        }
        __syncthreads();

        float* o = out + ((size_t)b * T_ + t0) * (size_t)GG;
        #pragma unroll
        for (int gi = 0; gi < 3; ++gi) {
            int k = tid + gi * TPB;
            if (k < GG / 4) {
                float4 a0 = sm.g.rowsA[idx[gi][0]];
                float4 a1 = sm.g.rowsA[idx[gi][1]];
                float4 a2 = sm.g.rowsA[idx[gi][2]];
                float4 a3 = sm.g.rowsA[idx[gi][3]];
                __stcs(reinterpret_cast<float4*>(o + 0 * GG) + k,
                       make_float4(a0.x, a1.x, a2.x, a3.x));
                __stcs(reinterpret_cast<float4*>(o + 1 * GG) + k,
                       make_float4(a0.y, a1.y, a2.y, a3.y));
                __stcs(reinterpret_cast<float4*>(o + 2 * GG) + k,
                       make_float4(a0.z, a1.z, a2.z, a3.z));
                __stcs(reinterpret_cast<float4*>(o + 3 * GG) + k,
                       make_float4(a0.w, a1.w, a2.w, a3.w));
                float4 b0 = sm.g.rowsB[idx[gi][0]];
                float4 b1 = sm.g.rowsB[idx[gi][1]];
                float4 b2 = sm.g.rowsB[idx[gi][2]];
                float4 b3 = sm.g.rowsB[idx[gi][3]];
                __stcs(reinterpret_cast<float4*>(o + 4 * GG) + k,
                       make_float4(b0.x, b1.x, b2.x, b3.x));
                __stcs(reinterpret_cast<float4*>(o + 5 * GG) + k,
                       make_float4(b0.y, b1.y, b2.y, b3.y));
                __stcs(reinterpret_cast<float4*>(o + 6 * GG) + k,
                       make_float4(b0.z, b1.z, b2.z, b3.z));
                __stcs(reinterpret_cast<float4*>(o + 7 * GG) + k,
                       make_float4(b0.w, b1.w, b2.w, b3.w));
            }
        }
    }

    // ---- replay-safe reset: last block to finish clears all counters ------
    if (tid == 0) {
        unsigned f = atomicAdd(&g_finish, 1u);
        if (f == gridDim.x - 1u) {
            g_arrive = 0u;
            g_ticket = 0u;
            g_finish = 0u;
            __threadfence();
        }
    }
}

// ---------------------------------------------------------------------------
extern "C" void kernel_launch(void* const* d_in, const int* in_sizes, int n_in,
                              void* d_out, int out_size) {
    const float* data = (const float*)d_in[0];
    const float* locs = (const float*)d_in[1];
    if (n_in >= 2 && in_sizes[0] < in_sizes[1]) {
        data = (const float*)d_in[1];
        locs = (const float*)d_in[0];
    }
    float* out = (float*)d_out;

    int sms = 148;                               // B200 default; query to be exact
    cudaDeviceGetAttribute(&sms, cudaDevAttrMultiProcessorCount, 0);
    const int grid = sms * 3;                    // == guaranteed-resident set

    persistent_kernel<<<grid, TPB>>>(data, locs, out);
}